// round 4
// baseline (speedup 1.0000x reference)
#include <cuda_runtime.h>
#include <cstdint>

#define N_NODES_MAX 100000
#define E_MAX 600000
#define CH 128

// Scratch (allocation-free rule: __device__ globals)
__device__ float g_h[N_NODES_MAX * CH];
__device__ int   g_deg[N_NODES_MAX];
__device__ float g_dinv[N_NODES_MAX];
__device__ int   g_off[N_NODES_MAX + 1];
__device__ int   g_cur[N_NODES_MAX];
__device__ int   g_srcs[E_MAX];

// ---------------------------------------------------------------------------
// SGEMM: H[M,128] = X[M,128] * W[128,128]
// BM=128, BN=128, BK=16, 256 threads, 8x8 micro-tile, smem double buffer.
__global__ __launch_bounds__(256, 2)
void k_gemm(const float* __restrict__ X, const float* __restrict__ W, int M) {
    __shared__ float As[2][16][132];   // [stage][k][row], pad to reduce STS conflicts
    __shared__ float Bs[2][16][128];   // [stage][k][col]

    const int tid = threadIdx.x;
    const int block_row = blockIdx.x * 128;
    const int tr = tid >> 4;           // 0..15
    const int tc = tid & 15;           // 0..15

    // loader indexing
    const int arow = tid >> 2;         // 0..63 (and +64)
    const int akc  = (tid & 3) * 4;    // k offset within chunk: 0,4,8,12
    const int brow = tid >> 5;         // 0..7 (and +8)
    const int bc4  = (tid & 31) * 4;   // 0..124

    float4 a0, a1, b0, b1;

    float acc[8][8];
#pragma unroll
    for (int i = 0; i < 8; i++)
#pragma unroll
        for (int j = 0; j < 8; j++) acc[i][j] = 0.f;

#define LOAD_REGS(k0)                                                          \
    {                                                                          \
        int r0 = block_row + arow;                                             \
        int r1 = r0 + 64;                                                      \
        a0 = (r0 < M) ? *(const float4*)(X + (size_t)r0 * CH + (k0) + akc)     \
                      : make_float4(0.f, 0.f, 0.f, 0.f);                       \
        a1 = (r1 < M) ? *(const float4*)(X + (size_t)r1 * CH + (k0) + akc)     \
                      : make_float4(0.f, 0.f, 0.f, 0.f);                       \
        b0 = *(const float4*)(W + (size_t)((k0) + brow) * CH + bc4);           \
        b1 = *(const float4*)(W + (size_t)((k0) + brow + 8) * CH + bc4);       \
    }

#define STORE_SMEM(s)                                                          \
    {                                                                          \
        As[s][akc + 0][arow] = a0.x;  As[s][akc + 1][arow] = a0.y;             \
        As[s][akc + 2][arow] = a0.z;  As[s][akc + 3][arow] = a0.w;             \
        As[s][akc + 0][arow + 64] = a1.x;  As[s][akc + 1][arow + 64] = a1.y;   \
        As[s][akc + 2][arow + 64] = a1.z;  As[s][akc + 3][arow + 64] = a1.w;   \
        *(float4*)&Bs[s][brow][bc4]     = b0;                                  \
        *(float4*)&Bs[s][brow + 8][bc4] = b1;                                  \
    }

    LOAD_REGS(0);
    STORE_SMEM(0);
    __syncthreads();

#pragma unroll
    for (int c = 0; c < 8; c++) {
        if (c < 7) LOAD_REGS((c + 1) * 16);
        const int s = c & 1;
#pragma unroll
        for (int k = 0; k < 16; k++) {
            float a[8], b[8];
#pragma unroll
            for (int i = 0; i < 8; i++) a[i] = As[s][k][tr * 8 + i];
#pragma unroll
            for (int j = 0; j < 8; j++) b[j] = Bs[s][k][tc * 8 + j];
#pragma unroll
            for (int i = 0; i < 8; i++)
#pragma unroll
                for (int j = 0; j < 8; j++) acc[i][j] = fmaf(a[i], b[j], acc[i][j]);
        }
        if (c < 7) {
            STORE_SMEM((c + 1) & 1);
            __syncthreads();
        }
    }

#pragma unroll
    for (int i = 0; i < 8; i++) {
        int grow = block_row + tr * 8 + i;
        if (grow < M) {
            float* hp = g_h + (size_t)grow * CH + tc * 8;
            *(float4*)(hp + 0) = make_float4(acc[i][0], acc[i][1], acc[i][2], acc[i][3]);
            *(float4*)(hp + 4) = make_float4(acc[i][4], acc[i][5], acc[i][6], acc[i][7]);
        }
    }
#undef LOAD_REGS
#undef STORE_SMEM
}

// ---------------------------------------------------------------------------
__global__ void k_init_deg(int N) {
    int i = blockIdx.x * blockDim.x + threadIdx.x;
    if (i < N) g_deg[i] = 0;
}

__global__ void k_deg(const int* __restrict__ ei, int E, int N) {
    int e = blockIdx.x * blockDim.x + threadIdx.x;
    if (e < E) {
        int dst = ei[E + e];
        if ((unsigned)dst < (unsigned)N)
            atomicAdd(&g_deg[dst], 1);
    }
}

// scan of deg -> g_off/g_cur, plus dinv = rsqrt(deg+1), single block
__global__ void k_scan(int N) {
    __shared__ int sums[1024];
    int t = threadIdx.x;
    int chunk = (N + 1023) / 1024;
    int s0 = t * chunk;
    int s1 = min(s0 + chunk, N);
    int sum = 0;
    for (int i = s0; i < s1; i++) sum += g_deg[i];
    sums[t] = sum;
    __syncthreads();
    for (int off = 1; off < 1024; off <<= 1) {
        int v = (t >= off) ? sums[t - off] : 0;
        __syncthreads();
        sums[t] += v;
        __syncthreads();
    }
    int run = sums[t] - sum;
    for (int i = s0; i < s1; i++) {
        int d = g_deg[i];
        g_off[i] = run;
        g_cur[i] = run;
        g_dinv[i] = rsqrtf((float)(d + 1));
        run += d;
    }
    if (t == 1023) g_off[N] = sums[1023];
}

__global__ void k_fill(const int* __restrict__ ei, int E, int N) {
    int e = blockIdx.x * blockDim.x + threadIdx.x;
    if (e < E) {
        int src = ei[e];
        int dst = ei[E + e];
        if ((unsigned)dst < (unsigned)N && (unsigned)src < (unsigned)N) {
            int pos = atomicAdd(&g_cur[dst], 1);
            if ((unsigned)pos < (unsigned)E_MAX) g_srcs[pos] = src;
        }
    }
}

// ---------------------------------------------------------------------------
// Gather per dst node (one warp per node), 4-edge software pipeline.
__global__ void k_gather(const float* __restrict__ bias,
                         const float* __restrict__ pw,
                         float* __restrict__ out, int N) {
    int gtid = blockIdx.x * blockDim.x + threadIdx.x;
    int node = gtid >> 5;
    int lane = gtid & 31;
    if (node >= N) return;

    float dn = g_dinv[node];
    float4 hv = reinterpret_cast<const float4*>(g_h + (size_t)node * CH)[lane];
    float ws = dn * dn;
    float4 acc;
    acc.x = hv.x * ws; acc.y = hv.y * ws; acc.z = hv.z * ws; acc.w = hv.w * ws;

    int s = g_off[node];
    int e = g_off[node + 1];
    int i = s;
    for (; i + 4 <= e; i += 4) {
        int s0 = g_srcs[i + 0], s1 = g_srcs[i + 1];
        int s2 = g_srcs[i + 2], s3 = g_srcs[i + 3];
        float w0 = g_dinv[s0] * dn, w1 = g_dinv[s1] * dn;
        float w2 = g_dinv[s2] * dn, w3 = g_dinv[s3] * dn;
        float4 h0 = reinterpret_cast<const float4*>(g_h + (size_t)s0 * CH)[lane];
        float4 h1 = reinterpret_cast<const float4*>(g_h + (size_t)s1 * CH)[lane];
        float4 h2 = reinterpret_cast<const float4*>(g_h + (size_t)s2 * CH)[lane];
        float4 h3 = reinterpret_cast<const float4*>(g_h + (size_t)s3 * CH)[lane];
        acc.x = fmaf(h0.x, w0, acc.x); acc.y = fmaf(h0.y, w0, acc.y);
        acc.z = fmaf(h0.z, w0, acc.z); acc.w = fmaf(h0.w, w0, acc.w);
        acc.x = fmaf(h1.x, w1, acc.x); acc.y = fmaf(h1.y, w1, acc.y);
        acc.z = fmaf(h1.z, w1, acc.z); acc.w = fmaf(h1.w, w1, acc.w);
        acc.x = fmaf(h2.x, w2, acc.x); acc.y = fmaf(h2.y, w2, acc.y);
        acc.z = fmaf(h2.z, w2, acc.z); acc.w = fmaf(h2.w, w2, acc.w);
        acc.x = fmaf(h3.x, w3, acc.x); acc.y = fmaf(h3.y, w3, acc.y);
        acc.z = fmaf(h3.z, w3, acc.z); acc.w = fmaf(h3.w, w3, acc.w);
    }
    for (; i < e; i++) {
        int src = g_srcs[i];
        float w = g_dinv[src] * dn;
        float4 h = reinterpret_cast<const float4*>(g_h + (size_t)src * CH)[lane];
        acc.x = fmaf(h.x, w, acc.x); acc.y = fmaf(h.y, w, acc.y);
        acc.z = fmaf(h.z, w, acc.z); acc.w = fmaf(h.w, w, acc.w);
    }

    float4 bb = reinterpret_cast<const float4*>(bias)[lane];
    acc.x += bb.x; acc.y += bb.y; acc.z += bb.z; acc.w += bb.w;

    float4 p = reinterpret_cast<const float4*>(pw)[lane];
    acc.x = acc.x >= 0.f ? acc.x : p.x * acc.x;
    acc.y = acc.y >= 0.f ? acc.y : p.y * acc.y;
    acc.z = acc.z >= 0.f ? acc.z : p.z * acc.z;
    acc.w = acc.w >= 0.f ? acc.w : p.w * acc.w;

    reinterpret_cast<float4*>(out + (size_t)node * CH)[lane] = acc;
}

// ---------------------------------------------------------------------------
extern "C" void kernel_launch(void* const* d_in, const int* in_sizes, int n_in,
                              void* d_out, int out_size) {
    const float* x  = (const float*)d_in[0];
    const int*   ei = (const int*)d_in[1];   // int64 in reference -> int32 on device
    const float* W  = (const float*)d_in[2];
    const float* b  = (const float*)d_in[3];
    const float* pw = (const float*)d_in[4];
    float* out = (float*)d_out;

    const int N = in_sizes[0] / CH;          // 100000
    const int E = in_sizes[1] / 2;           // 600000

    const int T = 256;

    // launch order chosen so ncu (-s 5 -c 1) captures k_gather at slot 6
    k_gemm<<<(N + 127) / 128, 256>>>(x, W, N);          // 1
    k_init_deg<<<(N + T - 1) / T, T>>>(N);              // 2
    k_deg<<<(E + T - 1) / T, T>>>(ei, E, N);            // 3
    k_scan<<<1, 1024>>>(N);                             // 4
    k_fill<<<(E + T - 1) / T, T>>>(ei, E, N);           // 5

    long long gthreads = (long long)N * 32;
    k_gather<<<(int)((gthreads + T - 1) / T), T>>>(b, pw, out, N);  // 6
}

// round 5
// speedup vs baseline: 2.2641x; 2.2641x over previous
#include <cuda_runtime.h>
#include <cstdint>

#define N_NODES_MAX 100000
#define E_MAX 600000
#define CH 128
#define SCAN_T 256
#define NB_MAX 512   // ceil(100000/256)=391 block partials

// Scratch (allocation-free rule: __device__ globals)
__device__ float g_h[N_NODES_MAX * CH];
__device__ int   g_deg[N_NODES_MAX];
__device__ float g_dinv[N_NODES_MAX];
__device__ int   g_off[N_NODES_MAX + 1];
__device__ int   g_cur[N_NODES_MAX];
__device__ int   g_srcs[E_MAX];
__device__ int   g_bsum[NB_MAX];
__device__ int   g_bpre[NB_MAX];

// ---------------------------------------------------------------------------
// SGEMM: H[M,128] = X[M,128] * W[128,128]  (R3 version: BM=BN=128, BK=8)
// Also zeroes g_deg (fused init).
__global__ void k_gemm(const float* __restrict__ X, const float* __restrict__ W,
                       int M) {
    __shared__ float As[8][128];   // [k][row]
    __shared__ float Bs[8][128];   // [k][col]

    const int tid = threadIdx.x;
    const int block_row = blockIdx.x * 128;
    const int tr = tid >> 4;       // 0..15
    const int tc = tid & 15;       // 0..15

    // fused: zero g_deg (grid covers >= M threads at 128 rows/block * 256 thr)
    {
        int gi = blockIdx.x * 256 + tid;
        if (gi < M) g_deg[gi] = 0;
        int gi2 = gi + gridDim.x * 256;
        if (gi2 < M) g_deg[gi2] = 0;
    }

    float acc[8][8];
#pragma unroll
    for (int i = 0; i < 8; i++)
#pragma unroll
        for (int j = 0; j < 8; j++) acc[i][j] = 0.f;

    for (int k0 = 0; k0 < 128; k0 += 8) {
        {
            int row = tid >> 1;                 // 0..127
            int kc  = (tid & 1) * 4;            // 0 or 4
            int grow = block_row + row;
            float4 v = make_float4(0.f, 0.f, 0.f, 0.f);
            if (grow < M)
                v = *reinterpret_cast<const float4*>(X + (size_t)grow * CH + k0 + kc);
            As[kc + 0][row] = v.x;
            As[kc + 1][row] = v.y;
            As[kc + 2][row] = v.z;
            As[kc + 3][row] = v.w;
        }
        {
            int row = tid >> 5;                 // 0..7
            int c4  = (tid & 31) * 4;           // 0..124
            float4 v = *reinterpret_cast<const float4*>(W + (size_t)(k0 + row) * CH + c4);
            *reinterpret_cast<float4*>(&Bs[row][c4]) = v;
        }
        __syncthreads();

#pragma unroll
        for (int k = 0; k < 8; k++) {
            float a[8], b[8];
#pragma unroll
            for (int i = 0; i < 8; i++) a[i] = As[k][tr * 8 + i];
#pragma unroll
            for (int j = 0; j < 8; j++) b[j] = Bs[k][tc * 8 + j];
#pragma unroll
            for (int i = 0; i < 8; i++)
#pragma unroll
                for (int j = 0; j < 8; j++) acc[i][j] = fmaf(a[i], b[j], acc[i][j]);
        }
        __syncthreads();
    }

#pragma unroll
    for (int i = 0; i < 8; i++) {
        int grow = block_row + tr * 8 + i;
        if (grow < M) {
            float* hp = g_h + (size_t)grow * CH + tc * 8;
            *(float4*)(hp + 0) = make_float4(acc[i][0], acc[i][1], acc[i][2], acc[i][3]);
            *(float4*)(hp + 4) = make_float4(acc[i][4], acc[i][5], acc[i][6], acc[i][7]);
        }
    }
}

// ---------------------------------------------------------------------------
__global__ void k_deg(const int* __restrict__ ei, int E, int N) {
    int e = blockIdx.x * blockDim.x + threadIdx.x;
    if (e < E) {
        int dst = ei[E + e];
        if ((unsigned)dst < (unsigned)N)
            atomicAdd(&g_deg[dst], 1);
    }
}

// --- Parallel scan, phase A: per-block sums of deg ---
__global__ void k_scanA(int N) {
    __shared__ int red[SCAN_T];
    int i = blockIdx.x * SCAN_T + threadIdx.x;
    int v = (i < N) ? g_deg[i] : 0;
    red[threadIdx.x] = v;
    __syncthreads();
#pragma unroll
    for (int off = SCAN_T / 2; off > 0; off >>= 1) {
        if (threadIdx.x < off) red[threadIdx.x] += red[threadIdx.x + off];
        __syncthreads();
    }
    if (threadIdx.x == 0) g_bsum[blockIdx.x] = red[0];
}

// --- Phase B: single small block scans the block partials (NB <= 512) ---
__global__ void k_scanB(int NB, int N) {
    __shared__ int s[NB_MAX];
    int t = threadIdx.x;
    int v = (t < NB) ? g_bsum[t] : 0;
    s[t] = v;
    __syncthreads();
#pragma unroll
    for (int off = 1; off < NB_MAX; off <<= 1) {
        int add = (t >= off) ? s[t - off] : 0;
        __syncthreads();
        s[t] += add;
        __syncthreads();
    }
    if (t < NB) g_bpre[t] = s[t] - v;        // exclusive
    if (t == NB_MAX - 1) g_off[N] = s[NB_MAX - 1];  // total edges kept
}

// --- Phase C: per-block local exclusive scan + write off/cur/dinv ---
__global__ void k_scanC(int N) {
    __shared__ int s[SCAN_T];
    int t = threadIdx.x;
    int i = blockIdx.x * SCAN_T + t;
    int d = (i < N) ? g_deg[i] : 0;
    s[t] = d;
    __syncthreads();
#pragma unroll
    for (int off = 1; off < SCAN_T; off <<= 1) {
        int add = (t >= off) ? s[t - off] : 0;
        __syncthreads();
        s[t] += add;
        __syncthreads();
    }
    if (i < N) {
        int pre = g_bpre[blockIdx.x] + s[t] - d;   // exclusive global prefix
        g_off[i] = pre;
        g_cur[i] = pre;
        g_dinv[i] = rsqrtf((float)(d + 1));
    }
}

// ---------------------------------------------------------------------------
__global__ void k_fill(const int* __restrict__ ei, int E, int N) {
    int e = blockIdx.x * blockDim.x + threadIdx.x;
    if (e < E) {
        int src = ei[e];
        int dst = ei[E + e];
        if ((unsigned)dst < (unsigned)N && (unsigned)src < (unsigned)N) {
            int pos = atomicAdd(&g_cur[dst], 1);
            if ((unsigned)pos < (unsigned)E_MAX) g_srcs[pos] = src;
        }
    }
}

// ---------------------------------------------------------------------------
// Gather per dst node (one warp per node), 4-edge software pipeline.
__global__ void k_gather(const float* __restrict__ bias,
                         const float* __restrict__ pw,
                         float* __restrict__ out, int N) {
    int gtid = blockIdx.x * blockDim.x + threadIdx.x;
    int node = gtid >> 5;
    int lane = gtid & 31;
    if (node >= N) return;

    float dn = g_dinv[node];
    float4 hv = reinterpret_cast<const float4*>(g_h + (size_t)node * CH)[lane];
    float ws = dn * dn;
    float4 acc;
    acc.x = hv.x * ws; acc.y = hv.y * ws; acc.z = hv.z * ws; acc.w = hv.w * ws;

    int s = g_off[node];
    int e = g_off[node + 1];
    int i = s;
    for (; i + 4 <= e; i += 4) {
        int s0 = g_srcs[i + 0], s1 = g_srcs[i + 1];
        int s2 = g_srcs[i + 2], s3 = g_srcs[i + 3];
        float w0 = g_dinv[s0] * dn, w1 = g_dinv[s1] * dn;
        float w2 = g_dinv[s2] * dn, w3 = g_dinv[s3] * dn;
        float4 h0 = reinterpret_cast<const float4*>(g_h + (size_t)s0 * CH)[lane];
        float4 h1 = reinterpret_cast<const float4*>(g_h + (size_t)s1 * CH)[lane];
        float4 h2 = reinterpret_cast<const float4*>(g_h + (size_t)s2 * CH)[lane];
        float4 h3 = reinterpret_cast<const float4*>(g_h + (size_t)s3 * CH)[lane];
        acc.x = fmaf(h0.x, w0, acc.x); acc.y = fmaf(h0.y, w0, acc.y);
        acc.z = fmaf(h0.z, w0, acc.z); acc.w = fmaf(h0.w, w0, acc.w);
        acc.x = fmaf(h1.x, w1, acc.x); acc.y = fmaf(h1.y, w1, acc.y);
        acc.z = fmaf(h1.z, w1, acc.z); acc.w = fmaf(h1.w, w1, acc.w);
        acc.x = fmaf(h2.x, w2, acc.x); acc.y = fmaf(h2.y, w2, acc.y);
        acc.z = fmaf(h2.z, w2, acc.z); acc.w = fmaf(h2.w, w2, acc.w);
        acc.x = fmaf(h3.x, w3, acc.x); acc.y = fmaf(h3.y, w3, acc.y);
        acc.z = fmaf(h3.z, w3, acc.z); acc.w = fmaf(h3.w, w3, acc.w);
    }
    for (; i < e; i++) {
        int src = g_srcs[i];
        float w = g_dinv[src] * dn;
        float4 h = reinterpret_cast<const float4*>(g_h + (size_t)src * CH)[lane];
        acc.x = fmaf(h.x, w, acc.x); acc.y = fmaf(h.y, w, acc.y);
        acc.z = fmaf(h.z, w, acc.z); acc.w = fmaf(h.w, w, acc.w);
    }

    float4 bb = reinterpret_cast<const float4*>(bias)[lane];
    acc.x += bb.x; acc.y += bb.y; acc.z += bb.z; acc.w += bb.w;

    float4 p = reinterpret_cast<const float4*>(pw)[lane];
    acc.x = acc.x >= 0.f ? acc.x : p.x * acc.x;
    acc.y = acc.y >= 0.f ? acc.y : p.y * acc.y;
    acc.z = acc.z >= 0.f ? acc.z : p.z * acc.z;
    acc.w = acc.w >= 0.f ? acc.w : p.w * acc.w;

    reinterpret_cast<float4*>(out + (size_t)node * CH)[lane] = acc;
}

// ---------------------------------------------------------------------------
extern "C" void kernel_launch(void* const* d_in, const int* in_sizes, int n_in,
                              void* d_out, int out_size) {
    const float* x  = (const float*)d_in[0];
    const int*   ei = (const int*)d_in[1];   // int64 in reference -> int32 on device
    const float* W  = (const float*)d_in[2];
    const float* b  = (const float*)d_in[3];
    const float* pw = (const float*)d_in[4];
    float* out = (float*)d_out;

    const int N = in_sizes[0] / CH;          // 100000
    const int E = in_sizes[1] / 2;           // 600000
    const int T = 256;
    const int NB = (N + SCAN_T - 1) / SCAN_T;  // 391

    k_gemm<<<(N + 127) / 128, 256>>>(x, W, N);   // also zeroes g_deg
    k_deg<<<(E + T - 1) / T, T>>>(ei, E, N);
    k_scanA<<<NB, SCAN_T>>>(N);
    k_scanB<<<1, NB_MAX>>>(NB, N);
    k_scanC<<<NB, SCAN_T>>>(N);
    k_fill<<<(E + T - 1) / T, T>>>(ei, E, N);

    long long gthreads = (long long)N * 32;
    k_gather<<<(int)((gthreads + T - 1) / T), T>>>(b, pw, out, N);
}

// round 6
// speedup vs baseline: 3.2289x; 1.4261x over previous
#include <cuda_runtime.h>
#include <cuda_bf16.h>
#include <cstdint>

#define N_NODES_MAX 100000
#define E_MAX 600000
#define CH 128
#define SCAN_T 256
#define NB_MAX 512   // ceil(100000/256)=391 block partials

// Scratch (allocation-free rule: __device__ globals)
__device__ float g_h[N_NODES_MAX * CH];
__device__ int   g_deg[N_NODES_MAX];
__device__ float g_dinv[N_NODES_MAX];
__device__ int   g_off[N_NODES_MAX + 1];
__device__ int   g_cur[N_NODES_MAX];
__device__ int   g_srcs[E_MAX];
__device__ int   g_bsum[NB_MAX];
__device__ int   g_bpre[NB_MAX];

// ---------------------------------------------------------------------------
// Tensor-core GEMM: H[M,128] = X[M,128] * W[128,128]
// Split bf16: x = xh+xl, W = wh+wl;  h = xh*wh + xh*wl + xl*wh  (fp32 acc)
// Block: 128 rows, 512 threads (16 warps), warp tile 16x64.
// smem: xs_hi/xs_lo [128][136], ws_hi/ws_lo (transposed, [n][k]) [128][136]
#define XS_STRIDE 136
#define TILE_BYTES (128 * XS_STRIDE * 2)   // 34816 per array

__device__ __forceinline__ void mma_bf16(float* c, const uint32_t* a, const uint32_t* b) {
    asm volatile(
        "mma.sync.aligned.m16n8k16.row.col.f32.bf16.bf16.f32 "
        "{%0,%1,%2,%3}, {%4,%5,%6,%7}, {%8,%9}, {%0,%1,%2,%3};"
        : "+f"(c[0]), "+f"(c[1]), "+f"(c[2]), "+f"(c[3])
        : "r"(a[0]), "r"(a[1]), "r"(a[2]), "r"(a[3]), "r"(b[0]), "r"(b[1]));
}

__global__ __launch_bounds__(512)
void k_gemm(const float* __restrict__ X, const float* __restrict__ W, int M) {
    extern __shared__ char smem[];
    __nv_bfloat16* xs_hi = (__nv_bfloat16*)(smem);
    __nv_bfloat16* xs_lo = (__nv_bfloat16*)(smem + TILE_BYTES);
    __nv_bfloat16* ws_hi = (__nv_bfloat16*)(smem + 2 * TILE_BYTES);
    __nv_bfloat16* ws_lo = (__nv_bfloat16*)(smem + 3 * TILE_BYTES);

    const int tid = threadIdx.x;
    const int block_row = blockIdx.x * 128;

    // fused: zero g_deg
    {
        int gi = blockIdx.x * 512 + tid;
        if (gi < M) g_deg[gi] = 0;
    }

    // fill ws (transposed [n][k]) with hi/lo split: 16384 elems / 512 thr = 32
#pragma unroll
    for (int i = 0; i < 32; i++) {
        int idx = tid + i * 512;
        int k = idx >> 7;
        int n = idx & 127;
        float v = W[idx];
        __nv_bfloat16 h = __float2bfloat16_rn(v);
        __nv_bfloat16 l = __float2bfloat16_rn(v - __bfloat162float(h));
        ws_hi[n * XS_STRIDE + k] = h;
        ws_lo[n * XS_STRIDE + k] = l;
    }

    // fill xs: 128 rows x 128 cols = 4096 float4, 8 per thread
#pragma unroll
    for (int i = 0; i < 8; i++) {
        int idx = tid + i * 512;
        int row = idx >> 5;
        int c4 = (idx & 31) * 4;
        int grow = block_row + row;
        float4 v = make_float4(0.f, 0.f, 0.f, 0.f);
        if (grow < M) v = *(const float4*)(X + (size_t)grow * CH + c4);
        float vv[4] = {v.x, v.y, v.z, v.w};
#pragma unroll
        for (int j = 0; j < 4; j++) {
            __nv_bfloat16 h = __float2bfloat16_rn(vv[j]);
            __nv_bfloat16 l = __float2bfloat16_rn(vv[j] - __bfloat162float(h));
            xs_hi[row * XS_STRIDE + c4 + j] = h;
            xs_lo[row * XS_STRIDE + c4 + j] = l;
        }
    }
    __syncthreads();

    const int warp = tid >> 5;
    const int lane = tid & 31;
    const int wr = (warp >> 1) * 16;    // warp row offset (0..112)
    const int wc = (warp & 1) * 64;     // warp col offset (0 or 64)
    const int g = lane >> 2;            // 0..7
    const int q = lane & 3;             // 0..3

    float acc[8][4];
#pragma unroll
    for (int nt = 0; nt < 8; nt++)
#pragma unroll
        for (int j = 0; j < 4; j++) acc[nt][j] = 0.f;

#pragma unroll
    for (int kc = 0; kc < 8; kc++) {
        const int k0 = kc * 16;
        const int r0 = (wr + g) * XS_STRIDE;
        const int r1 = (wr + g + 8) * XS_STRIDE;
        const int c0 = k0 + q * 2;
        uint32_t a_hi[4], a_lo[4];
        a_hi[0] = *(const uint32_t*)&xs_hi[r0 + c0];
        a_hi[1] = *(const uint32_t*)&xs_hi[r1 + c0];
        a_hi[2] = *(const uint32_t*)&xs_hi[r0 + c0 + 8];
        a_hi[3] = *(const uint32_t*)&xs_hi[r1 + c0 + 8];
        a_lo[0] = *(const uint32_t*)&xs_lo[r0 + c0];
        a_lo[1] = *(const uint32_t*)&xs_lo[r1 + c0];
        a_lo[2] = *(const uint32_t*)&xs_lo[r0 + c0 + 8];
        a_lo[3] = *(const uint32_t*)&xs_lo[r1 + c0 + 8];

#pragma unroll
        for (int nt = 0; nt < 8; nt++) {
            const int n = wc + nt * 8 + g;
            uint32_t b_hi[2], b_lo[2];
            b_hi[0] = *(const uint32_t*)&ws_hi[n * XS_STRIDE + c0];
            b_hi[1] = *(const uint32_t*)&ws_hi[n * XS_STRIDE + c0 + 8];
            b_lo[0] = *(const uint32_t*)&ws_lo[n * XS_STRIDE + c0];
            b_lo[1] = *(const uint32_t*)&ws_lo[n * XS_STRIDE + c0 + 8];
            mma_bf16(acc[nt], a_hi, b_hi);
            mma_bf16(acc[nt], a_hi, b_lo);
            mma_bf16(acc[nt], a_lo, b_hi);
        }
    }

    // epilogue: write 16x64 warp tile to g_h
    const int row0 = block_row + wr + g;
    const int row1 = row0 + 8;
#pragma unroll
    for (int nt = 0; nt < 8; nt++) {
        const int col = wc + nt * 8 + q * 2;
        if (row0 < M)
            *(float2*)(g_h + (size_t)row0 * CH + col) = make_float2(acc[nt][0], acc[nt][1]);
        if (row1 < M)
            *(float2*)(g_h + (size_t)row1 * CH + col) = make_float2(acc[nt][2], acc[nt][3]);
    }
}

// ---------------------------------------------------------------------------
__global__ void k_deg(const int* __restrict__ ei, int E, int N) {
    int e = blockIdx.x * blockDim.x + threadIdx.x;
    if (e < E) {
        int dst = ei[E + e];
        if ((unsigned)dst < (unsigned)N)
            atomicAdd(&g_deg[dst], 1);
    }
}

// --- Parallel scan, phase A: per-block sums of deg ---
__global__ void k_scanA(int N) {
    __shared__ int red[SCAN_T];
    int i = blockIdx.x * SCAN_T + threadIdx.x;
    int v = (i < N) ? g_deg[i] : 0;
    red[threadIdx.x] = v;
    __syncthreads();
#pragma unroll
    for (int off = SCAN_T / 2; off > 0; off >>= 1) {
        if (threadIdx.x < off) red[threadIdx.x] += red[threadIdx.x + off];
        __syncthreads();
    }
    if (threadIdx.x == 0) g_bsum[blockIdx.x] = red[0];
}

// --- Phase B: single block scans the block partials ---
__global__ void k_scanB(int NB, int N) {
    __shared__ int s[NB_MAX];
    int t = threadIdx.x;
    int v = (t < NB) ? g_bsum[t] : 0;
    s[t] = v;
    __syncthreads();
#pragma unroll
    for (int off = 1; off < NB_MAX; off <<= 1) {
        int add = (t >= off) ? s[t - off] : 0;
        __syncthreads();
        s[t] += add;
        __syncthreads();
    }
    if (t < NB) g_bpre[t] = s[t] - v;
    if (t == NB_MAX - 1) g_off[N] = s[NB_MAX - 1];
}

// --- Phase C: per-block local exclusive scan + write off/cur/dinv ---
__global__ void k_scanC(int N) {
    __shared__ int s[SCAN_T];
    int t = threadIdx.x;
    int i = blockIdx.x * SCAN_T + t;
    int d = (i < N) ? g_deg[i] : 0;
    s[t] = d;
    __syncthreads();
#pragma unroll
    for (int off = 1; off < SCAN_T; off <<= 1) {
        int add = (t >= off) ? s[t - off] : 0;
        __syncthreads();
        s[t] += add;
        __syncthreads();
    }
    if (i < N) {
        int pre = g_bpre[blockIdx.x] + s[t] - d;
        g_off[i] = pre;
        g_cur[i] = pre;
        g_dinv[i] = rsqrtf((float)(d + 1));
    }
}

// ---------------------------------------------------------------------------
__global__ void k_fill(const int* __restrict__ ei, int E, int N) {
    int e = blockIdx.x * blockDim.x + threadIdx.x;
    if (e < E) {
        int src = ei[e];
        int dst = ei[E + e];
        if ((unsigned)dst < (unsigned)N && (unsigned)src < (unsigned)N) {
            int pos = atomicAdd(&g_cur[dst], 1);
            if ((unsigned)pos < (unsigned)E_MAX) g_srcs[pos] = src;
        }
    }
}

// ---------------------------------------------------------------------------
// Gather per dst node (one warp per node), 4-edge software pipeline.
__global__ void k_gather(const float* __restrict__ bias,
                         const float* __restrict__ pw,
                         float* __restrict__ out, int N) {
    int gtid = blockIdx.x * blockDim.x + threadIdx.x;
    int node = gtid >> 5;
    int lane = gtid & 31;
    if (node >= N) return;

    float dn = g_dinv[node];
    float4 hv = reinterpret_cast<const float4*>(g_h + (size_t)node * CH)[lane];
    float ws = dn * dn;
    float4 acc;
    acc.x = hv.x * ws; acc.y = hv.y * ws; acc.z = hv.z * ws; acc.w = hv.w * ws;

    int s = g_off[node];
    int e = g_off[node + 1];
    int i = s;
    for (; i + 4 <= e; i += 4) {
        int s0 = g_srcs[i + 0], s1 = g_srcs[i + 1];
        int s2 = g_srcs[i + 2], s3 = g_srcs[i + 3];
        float w0 = g_dinv[s0] * dn, w1 = g_dinv[s1] * dn;
        float w2 = g_dinv[s2] * dn, w3 = g_dinv[s3] * dn;
        float4 h0 = reinterpret_cast<const float4*>(g_h + (size_t)s0 * CH)[lane];
        float4 h1 = reinterpret_cast<const float4*>(g_h + (size_t)s1 * CH)[lane];
        float4 h2 = reinterpret_cast<const float4*>(g_h + (size_t)s2 * CH)[lane];
        float4 h3 = reinterpret_cast<const float4*>(g_h + (size_t)s3 * CH)[lane];
        acc.x = fmaf(h0.x, w0, acc.x); acc.y = fmaf(h0.y, w0, acc.y);
        acc.z = fmaf(h0.z, w0, acc.z); acc.w = fmaf(h0.w, w0, acc.w);
        acc.x = fmaf(h1.x, w1, acc.x); acc.y = fmaf(h1.y, w1, acc.y);
        acc.z = fmaf(h1.z, w1, acc.z); acc.w = fmaf(h1.w, w1, acc.w);
        acc.x = fmaf(h2.x, w2, acc.x); acc.y = fmaf(h2.y, w2, acc.y);
        acc.z = fmaf(h2.z, w2, acc.z); acc.w = fmaf(h2.w, w2, acc.w);
        acc.x = fmaf(h3.x, w3, acc.x); acc.y = fmaf(h3.y, w3, acc.y);
        acc.z = fmaf(h3.z, w3, acc.z); acc.w = fmaf(h3.w, w3, acc.w);
    }
    for (; i < e; i++) {
        int src = g_srcs[i];
        float w = g_dinv[src] * dn;
        float4 h = reinterpret_cast<const float4*>(g_h + (size_t)src * CH)[lane];
        acc.x = fmaf(h.x, w, acc.x); acc.y = fmaf(h.y, w, acc.y);
        acc.z = fmaf(h.z, w, acc.z); acc.w = fmaf(h.w, w, acc.w);
    }

    float4 bb = reinterpret_cast<const float4*>(bias)[lane];
    acc.x += bb.x; acc.y += bb.y; acc.z += bb.z; acc.w += bb.w;

    float4 p = reinterpret_cast<const float4*>(pw)[lane];
    acc.x = acc.x >= 0.f ? acc.x : p.x * acc.x;
    acc.y = acc.y >= 0.f ? acc.y : p.y * acc.y;
    acc.z = acc.z >= 0.f ? acc.z : p.z * acc.z;
    acc.w = acc.w >= 0.f ? acc.w : p.w * acc.w;

    reinterpret_cast<float4*>(out + (size_t)node * CH)[lane] = acc;
}

// ---------------------------------------------------------------------------
extern "C" void kernel_launch(void* const* d_in, const int* in_sizes, int n_in,
                              void* d_out, int out_size) {
    const float* x  = (const float*)d_in[0];
    const int*   ei = (const int*)d_in[1];   // int64 in reference -> int32 on device
    const float* W  = (const float*)d_in[2];
    const float* b  = (const float*)d_in[3];
    const float* pw = (const float*)d_in[4];
    float* out = (float*)d_out;

    const int N = in_sizes[0] / CH;          // 100000
    const int E = in_sizes[1] / 2;           // 600000
    const int T = 256;
    const int NB = (N + SCAN_T - 1) / SCAN_T;

    const int GEMM_SMEM = 4 * TILE_BYTES;    // 139264 bytes
    cudaFuncSetAttribute(k_gemm, cudaFuncAttributeMaxDynamicSharedMemorySize, GEMM_SMEM);

    k_gemm<<<(N + 127) / 128, 512, GEMM_SMEM>>>(x, W, N);  // also zeroes g_deg
    k_deg<<<(E + T - 1) / T, T>>>(ei, E, N);
    k_scanA<<<NB, SCAN_T>>>(N);
    k_scanB<<<1, NB_MAX>>>(NB, N);
    k_scanC<<<NB, SCAN_T>>>(N);
    k_fill<<<(E + T - 1) / T, T>>>(ei, E, N);

    long long gthreads = (long long)N * 32;
    k_gather<<<(int)((gthreads + T - 1) / T), T>>>(b, pw, out, N);
}